// round 1
// baseline (speedup 1.0000x reference)
#include <cuda_runtime.h>

// Problem constants
#define E_TOTAL 625000
#define DZ      128      // node feature dim
#define TWO_D   256      // concat dim (K of GEMM1)
#define HH      128      // hidden 1
#define HQ      64       // hidden 2
#define TILE_M  128      // edges per CTA
#define KB      16       // K-slice for GEMM1
#define NSTEP   (TWO_D / KB)   // 16
#define HS_STR  130      // padded stride for h1 in smem (bank-conflict-free phase-2 reads)

struct Smem {
    union {
        struct {
            float As[KB][TILE_M];   // 8 KB  (k-major gathered A slice)
            float Bs[KB][HH];       // 8 KB  (W1 slice)
        } ab;
        float W2s[HH][HQ];          // 32 KB (loaded after GEMM1 finishes)
    } u;
    float Hs[TILE_M][HS_STR];       // 66.56 KB (relu(h1))
    int sSrc[TILE_M];
    int sDst[TILE_M];
};

__global__ void __launch_bounds__(256, 2)
lp_kernel(const float* __restrict__ z,
          const void*  __restrict__ ei_raw,
          const float* __restrict__ W1,
          const float* __restrict__ b1,
          const float* __restrict__ W2,
          const float* __restrict__ b2,
          const float* __restrict__ W3,
          const float* __restrict__ b3,
          float* __restrict__ out)
{
    extern __shared__ char raw[];
    Smem& s = *reinterpret_cast<Smem*>(raw);
    const int tid   = threadIdx.x;
    const int tile0 = blockIdx.x * TILE_M;
    const int rem   = min(TILE_M, E_TOTAL - tile0);

    // ---- edge_index dtype sniff: int64 vs int32 ----
    // If int64 (values < 50000, nonneg), every odd int32 slot is a zero high word.
    // If int32, 32 consecutive odd slots being all zero has prob ~(2e-5)^32 = 0.
    const int* e32 = reinterpret_cast<const int*>(ei_raw);
    int hi = 0;
#pragma unroll
    for (int i = 0; i < 32; ++i) hi |= e32[2 * i + 1];
    const bool is64 = (hi == 0);

    if (tid < TILE_M) {
        int e = tile0 + ((tid < rem) ? tid : 0);
        if (is64) {
            const long long* e64 = reinterpret_cast<const long long*>(ei_raw);
            s.sSrc[tid] = (int)e64[e];
            s.sDst[tid] = (int)e64[E_TOTAL + e];
        } else {
            s.sSrc[tid] = e32[e];
            s.sDst[tid] = e32[E_TOTAL + e];
        }
    }
    __syncthreads();

    // =================== Phase 1: h1 = relu([z_i|z_j] @ W1 + b1) ===================
    // 128x128 output tile, K=256 in 16 slices of 16. 16x16 thread grid, 8x8 per thread.
    const int tx = tid & 15;   // col group: cols tx*8 .. tx*8+7
    const int ty = tid >> 4;   // row group: rows ty*8 .. ty*8+7

    float acc[8][8];
#pragma unroll
    for (int i = 0; i < 8; ++i)
#pragma unroll
        for (int j = 0; j < 8; ++j) acc[i][j] = 0.f;

    // A-tile loader mapping: thread pair per row; each thread loads 8 consecutive k.
    const int lm  = tid >> 1;          // row 0..127
    const int lk8 = (tid & 1) * 8;     // k offset within slice: 0 or 8
    const float* zsrc = z + (size_t)s.sSrc[lm] * DZ;
    const float* zdst = z + (size_t)s.sDst[lm] * DZ;

    for (int step = 0; step < NSTEP; ++step) {
        const int K0 = step * KB;
        // --- load gathered A slice: As[kk][m] = edge_feat[m][K0+kk] ---
        {
            const int k = K0 + lk8;                       // slice never straddles D boundary
            const float* zr = (k < DZ) ? (zsrc + k) : (zdst + (k - DZ));
            float4 v0 = *reinterpret_cast<const float4*>(zr);
            float4 v1 = *reinterpret_cast<const float4*>(zr + 4);
            s.u.ab.As[lk8 + 0][lm] = v0.x;
            s.u.ab.As[lk8 + 1][lm] = v0.y;
            s.u.ab.As[lk8 + 2][lm] = v0.z;
            s.u.ab.As[lk8 + 3][lm] = v0.w;
            s.u.ab.As[lk8 + 4][lm] = v1.x;
            s.u.ab.As[lk8 + 5][lm] = v1.y;
            s.u.ab.As[lk8 + 6][lm] = v1.z;
            s.u.ab.As[lk8 + 7][lm] = v1.w;
        }
        // --- load W1 slice: Bs[kk][n] ---
        {
            const int kk = tid >> 4;
            const int n0 = (tid & 15) << 3;
            const float* g = W1 + (size_t)(K0 + kk) * HH + n0;
            float4 w0 = *reinterpret_cast<const float4*>(g);
            float4 w1 = *reinterpret_cast<const float4*>(g + 4);
            *reinterpret_cast<float4*>(&s.u.ab.Bs[kk][n0])     = w0;
            *reinterpret_cast<float4*>(&s.u.ab.Bs[kk][n0 + 4]) = w1;
        }
        __syncthreads();

#pragma unroll
        for (int kk = 0; kk < KB; ++kk) {
            float a[8], b[8];
            *reinterpret_cast<float4*>(&a[0]) = *reinterpret_cast<const float4*>(&s.u.ab.As[kk][ty << 3]);
            *reinterpret_cast<float4*>(&a[4]) = *reinterpret_cast<const float4*>(&s.u.ab.As[kk][(ty << 3) + 4]);
            *reinterpret_cast<float4*>(&b[0]) = *reinterpret_cast<const float4*>(&s.u.ab.Bs[kk][tx << 3]);
            *reinterpret_cast<float4*>(&b[4]) = *reinterpret_cast<const float4*>(&s.u.ab.Bs[kk][(tx << 3) + 4]);
#pragma unroll
            for (int i = 0; i < 8; ++i)
#pragma unroll
                for (int j = 0; j < 8; ++j)
                    acc[i][j] = fmaf(a[i], b[j], acc[i][j]);
        }
        __syncthreads();
    }

    // --- epilogue 1: bias + relu -> Hs; stage W2 into the (now free) union region ---
    {
        const int col0 = tx << 3, row0 = ty << 3;
        float bb[8];
#pragma unroll
        for (int j = 0; j < 8; ++j) bb[j] = b1[col0 + j];
#pragma unroll
        for (int i = 0; i < 8; ++i)
#pragma unroll
            for (int j = 0; j < 8; ++j)
                s.Hs[row0 + i][col0 + j] = fmaxf(acc[i][j] + bb[j], 0.f);
    }
    for (int i = tid; i < (HH * HQ) / 4; i += 256)
        reinterpret_cast<float4*>(&s.u.W2s[0][0])[i] =
            reinterpret_cast<const float4*>(W2)[i];
    __syncthreads();

    // =================== Phase 2: h2 = relu(h1 @ W2 + b2) ===================
    // 128x64 output, K=128. 32x8 thread grid, 4 rows x 8 cols per thread.
    const int tx2 = tid & 7;
    const int ty2 = tid >> 3;
    const int c0  = tx2 << 3;   // cols c0 .. c0+7
    const int r0  = ty2 << 2;   // rows r0 .. r0+3

    float acc2[4][8];
#pragma unroll
    for (int i = 0; i < 4; ++i)
#pragma unroll
        for (int j = 0; j < 8; ++j) acc2[i][j] = 0.f;

#pragma unroll 4
    for (int k = 0; k < HH; ++k) {
        float a0 = s.Hs[r0 + 0][k];
        float a1 = s.Hs[r0 + 1][k];
        float a2 = s.Hs[r0 + 2][k];
        float a3 = s.Hs[r0 + 3][k];
        float w[8];
        *reinterpret_cast<float4*>(&w[0]) = *reinterpret_cast<const float4*>(&s.u.W2s[k][c0]);
        *reinterpret_cast<float4*>(&w[4]) = *reinterpret_cast<const float4*>(&s.u.W2s[k][c0 + 4]);
#pragma unroll
        for (int j = 0; j < 8; ++j) {
            acc2[0][j] = fmaf(a0, w[j], acc2[0][j]);
            acc2[1][j] = fmaf(a1, w[j], acc2[1][j]);
            acc2[2][j] = fmaf(a2, w[j], acc2[2][j]);
            acc2[3][j] = fmaf(a3, w[j], acc2[3][j]);
        }
    }

    // =================== Phase 3: scores = relu(h2) @ W3 + b3 ===================
    float w3[8], bb2[8];
#pragma unroll
    for (int j = 0; j < 8; ++j) { w3[j] = W3[c0 + j]; bb2[j] = b2[c0 + j]; }

    float p[4];
#pragma unroll
    for (int i = 0; i < 4; ++i) {
        float sum = 0.f;
#pragma unroll
        for (int j = 0; j < 8; ++j)
            sum += fmaxf(acc2[i][j] + bb2[j], 0.f) * w3[j];
        p[i] = sum;
    }
    // reduce across the 8 column-group lanes (tx2) sharing these rows
#pragma unroll
    for (int off = 4; off > 0; off >>= 1) {
        p[0] += __shfl_down_sync(0xffffffffu, p[0], off, 8);
        p[1] += __shfl_down_sync(0xffffffffu, p[1], off, 8);
        p[2] += __shfl_down_sync(0xffffffffu, p[2], off, 8);
        p[3] += __shfl_down_sync(0xffffffffu, p[3], off, 8);
    }
    if (tx2 == 0) {
        const float bias3 = b3[0];
#pragma unroll
        for (int i = 0; i < 4; ++i) {
            const int m = r0 + i;
            if (m < rem) out[tile0 + m] = p[i] + bias3;
        }
    }
}

extern "C" void kernel_launch(void* const* d_in, const int* in_sizes, int n_in,
                              void* d_out, int out_size)
{
    const float* z  = (const float*)d_in[0];
    const void*  ei = d_in[1];                 // int64 or int32, sniffed in-kernel
    const float* W1 = (const float*)d_in[2];
    const float* b1 = (const float*)d_in[3];
    const float* W2 = (const float*)d_in[4];
    const float* b2 = (const float*)d_in[5];
    const float* W3 = (const float*)d_in[6];
    const float* b3 = (const float*)d_in[7];
    float* out = (float*)d_out;

    cudaFuncSetAttribute(lp_kernel, cudaFuncAttributeMaxDynamicSharedMemorySize,
                         (int)sizeof(Smem));

    dim3 grid((E_TOTAL + TILE_M - 1) / TILE_M);   // 4883 CTAs
    lp_kernel<<<grid, 256, sizeof(Smem)>>>(z, ei, W1, b1, W2, b2, W3, b3, out);
}

// round 6
// speedup vs baseline: 1.4529x; 1.4529x over previous
#include <cuda_runtime.h>
#include <cstdint>

#define E_TOTAL 625000
#define DZ      128
#define HH      128
#define HQ      64
#define TILE_M  128
#define THREADS 256

// ---------------- SMEM layout (byte offsets) ----------------
// A slices (gathered edge features, fragment-order): 2 x 16 KB
// B slices (W1^ fragment-order):                      2 x 16 KB
// H (relu(h1), fragment-order for GEMM2 A):           64 KB
// W2F (W2 fragment-order for GEMM2 B):                32 KB
#define A0_OFF 0
#define A1_OFF 16384
#define B0_OFF 32768
#define B1_OFF 49152
#define H_OFF  65536
#define W2_OFF 131072
#define MISC   163840
#define SRCI   (MISC + 0)
#define DSTI   (MISC + 512)
#define B1S    (MISC + 1024)
#define B2S    (MISC + 1536)
#define W3S    (MISC + 1792)
#define OACC   (MISC + 2048)   // 128 rows x 4 warp-cols x f32 = 2 KB
#define SMEM_TOTAL (MISC + 4096)

// ---------------- helpers ----------------
__device__ __forceinline__ uint32_t smem_u32(const void* p) {
    uint32_t a;
    asm("{ .reg .u64 t; cvta.to.shared.u64 t, %1; cvt.u32.u64 %0, t; }"
        : "=r"(a) : "l"(p));
    return a;
}

__device__ __forceinline__ uint32_t f2tf(float f) {
    uint32_t u;
    asm("cvt.rna.tf32.f32 %0, %1;" : "=r"(u) : "f"(f));
    return u;
}

// m16n8k8 tf32 mma, fp32 accumulate (base sm_80 PTX — works on plain sm_103)
__device__ __forceinline__ void mma8(float* d,
                                     uint32_t a0, uint32_t a1, uint32_t a2, uint32_t a3,
                                     uint32_t b0, uint32_t b1) {
    asm volatile(
        "mma.sync.aligned.m16n8k8.row.col.f32.tf32.tf32.f32 "
        "{%0,%1,%2,%3}, {%4,%5,%6,%7}, {%8,%9}, {%0,%1,%2,%3};"
        : "+f"(d[0]), "+f"(d[1]), "+f"(d[2]), "+f"(d[3])
        : "r"(a0), "r"(a1), "r"(a2), "r"(a3), "r"(b0), "r"(b1));
}

#define LDS128(r, addr)                                                        \
    asm volatile("ld.shared.v4.b32 {%0,%1,%2,%3}, [%4];"                       \
        : "=r"((r)[0]), "=r"((r)[1]), "=r"((r)[2]), "=r"((r)[3]) : "r"(addr))

// ---- fragment-order address maps (byte offsets within region) ----
// A-frag (m16k8): per (mt=m>>4, ks=k>>3): 32 lanes x 16B; lane=(m&7)*4+(k&3);
// within 16B: +8 if (k&7)>=4 (a2/a3), +4 if (m&15)>=8 (a1/a3).
__device__ __forceinline__ int a_addr(int m, int k) {   // k in 0..31 (slice)
    return ((((m >> 4) * 4 + (k >> 3)) * 32 + (m & 7) * 4 + (k & 3)) << 4)
         + (((k & 7) >= 4) ? 8 : 0) + (((m & 15) >= 8) ? 4 : 0);
}
// B-frag pair (k8n8 x2): per (nt=n>>3, ksp=k>>4): lane=(n&7)*4+(k&3);
// within 16B: +8 for odd ks, +4 if (k&7)>=4 (b1).
__device__ __forceinline__ int b1_addr(int k, int n) {  // k in 0..31 (slice)
    return ((((n >> 3) * 2 + (k >> 4)) * 32 + (n & 7) * 4 + (k & 3)) << 4)
         + (((k >> 3) & 1) << 3) + (((k & 7) >= 4) ? 4 : 0);
}
__device__ __forceinline__ int h_addr(int m, int k) {   // k in 0..127
    return ((((m >> 4) * 16 + (k >> 3)) * 32 + (m & 7) * 4 + (k & 3)) << 4)
         + (((k & 7) >= 4) ? 8 : 0) + (((m & 15) >= 8) ? 4 : 0);
}
__device__ __forceinline__ int w2_addr(int k, int n) {  // k 0..127, n 0..63
    return ((((n >> 3) * 8 + (k >> 4)) * 32 + (n & 7) * 4 + (k & 3)) << 4)
         + (((k >> 3) & 1) << 3) + (((k & 7) >= 4) ? 4 : 0);
}

// ---------------- kernel ----------------
__global__ void __launch_bounds__(THREADS, 1)
lp_mma_kernel(const float* __restrict__ z,
              const void*  __restrict__ ei_raw,
              const float* __restrict__ W1,
              const float* __restrict__ b1,
              const float* __restrict__ W2,
              const float* __restrict__ b2,
              const float* __restrict__ W3,
              const float* __restrict__ b3,
              float* __restrict__ out)
{
    extern __shared__ char smem[];
    const uint32_t sb  = smem_u32(smem);
    const int tid      = threadIdx.x;
    const int lane     = tid & 31;
    const int wid      = tid >> 5;
    const int g        = lane >> 2;      // group id (row within 8)
    const int t4       = lane & 3;       // thread-in-group
    const int warp_m   = wid & 1;        // 2 m-warps (64 rows each)
    const int warp_n   = wid >> 1;       // 4 n-warps (32 cols each)
    const int tile0    = blockIdx.x * TILE_M;
    const int rem      = min(TILE_M, E_TOTAL - tile0);

    // ---- edge_index dtype sniff (int64 vs int32) + index staging ----
    const int* e32 = reinterpret_cast<const int*>(ei_raw);
    int hiw = 0;
#pragma unroll
    for (int i = 0; i < 32; ++i) hiw |= e32[2 * i + 1];
    const bool is64 = (hiw == 0);

    if (tid < TILE_M) {
        int e = tile0 + ((tid < rem) ? tid : 0);
        int si, di;
        if (is64) {
            const long long* e64 = reinterpret_cast<const long long*>(ei_raw);
            si = (int)e64[e];
            di = (int)e64[E_TOTAL + e];
        } else {
            si = e32[e];
            di = e32[E_TOTAL + e];
        }
        ((int*)(smem + SRCI))[tid] = si;
        ((int*)(smem + DSTI))[tid] = di;
        ((float*)(smem + B1S))[tid] = b1[tid];
    }
    if (tid < HQ) {
        ((float*)(smem + B2S))[tid] = b2[tid];
        ((float*)(smem + W3S))[tid] = W3[tid];
    }
    __syncthreads();

    // ---- loaders ----
    // gather A slice (k-step of 32): thread -> (m = tid&127, k-half = tid>>7)
    auto load_A = [&](int step, int buf_off) {
        const int m  = tid & 127;
        const int kh = tid >> 7;
        const int kg = step * 32 + kh * 16;                 // global k of chunk
        const int row = ((const int*)(smem + (kg < DZ ? SRCI : DSTI)))[m];
        const float* zr = z + (size_t)row * DZ + (kg & (DZ - 1));
        char* base = smem + buf_off;
#pragma unroll
        for (int q = 0; q < 4; ++q) {
            float4 v = __ldg(reinterpret_cast<const float4*>(zr + q * 4));
            const int kl = kh * 16 + q * 4;                 // k within slice
            *(uint32_t*)(base + a_addr(m, kl + 0)) = f2tf(v.x);
            *(uint32_t*)(base + a_addr(m, kl + 1)) = f2tf(v.y);
            *(uint32_t*)(base + a_addr(m, kl + 2)) = f2tf(v.z);
            *(uint32_t*)(base + a_addr(m, kl + 3)) = f2tf(v.w);
        }
    };
    // W1 slice: thread -> (kk = tid&31 within slice, n-16-chunk = tid>>5)
    auto load_B = [&](int step, int buf_off) {
        const int kk = tid & 31;
        const int nh = tid >> 5;
        const float* gp = W1 + (size_t)(step * 32 + kk) * HH + nh * 16;
        char* base = smem + buf_off;
#pragma unroll
        for (int q = 0; q < 4; ++q) {
            float4 v = __ldg(reinterpret_cast<const float4*>(gp + q * 4));
            const int n0 = nh * 16 + q * 4;
            *(uint32_t*)(base + b1_addr(kk, n0 + 0)) = f2tf(v.x);
            *(uint32_t*)(base + b1_addr(kk, n0 + 1)) = f2tf(v.y);
            *(uint32_t*)(base + b1_addr(kk, n0 + 2)) = f2tf(v.z);
            *(uint32_t*)(base + b1_addr(kk, n0 + 3)) = f2tf(v.w);
        }
    };

    // W2 fragment-order load (once; region untouched by GEMM1)
    {
        const int k  = tid >> 1;
        const int nh = tid & 1;
        const float* gp = W2 + (size_t)k * HQ + nh * 32;
        char* base = smem + W2_OFF;
#pragma unroll
        for (int q = 0; q < 8; ++q) {
            float4 v = __ldg(reinterpret_cast<const float4*>(gp + q * 4));
            const int n0 = nh * 32 + q * 4;
            *(uint32_t*)(base + w2_addr(k, n0 + 0)) = f2tf(v.x);
            *(uint32_t*)(base + w2_addr(k, n0 + 1)) = f2tf(v.y);
            *(uint32_t*)(base + w2_addr(k, n0 + 2)) = f2tf(v.z);
            *(uint32_t*)(base + w2_addr(k, n0 + 3)) = f2tf(v.w);
        }
    }

    load_A(0, A0_OFF);
    load_B(0, B0_OFF);
    __syncthreads();

    // =================== GEMM1: C = [z_i|z_j] @ W1 (K=256, 8 slices) ===================
    float acc[4][4][4];
#pragma unroll
    for (int i = 0; i < 4; ++i)
#pragma unroll
        for (int j = 0; j < 4; ++j)
#pragma unroll
            for (int c = 0; c < 4; ++c) acc[i][j][c] = 0.f;

#pragma unroll 1
    for (int step = 0; step < 8; ++step) {
        const int cur = step & 1;
        if (step < 7) {                       // prefetch next slice into other buffer
            load_A(step + 1, cur ? A0_OFF : A1_OFF);
            load_B(step + 1, cur ? B0_OFF : B1_OFF);
        }
        const uint32_t Ab = sb + (cur ? A1_OFF : A0_OFF) + ((warp_m * 16) << 9) + lane * 16;
        const uint32_t Bb = sb + (cur ? B1_OFF : B0_OFF) + ((warp_n * 8)  << 9) + lane * 16;

#pragma unroll
        for (int ksp = 0; ksp < 2; ++ksp) {
            uint32_t bp[4][4];
#pragma unroll
            for (int ntl = 0; ntl < 4; ++ntl)
                LDS128(bp[ntl], Bb + ((ntl * 2 + ksp) << 9));
#pragma unroll
            for (int kin = 0; kin < 2; ++kin) {
                const int ks = ksp * 2 + kin;
                uint32_t a[4][4];
#pragma unroll
                for (int mtl = 0; mtl < 4; ++mtl)
                    LDS128(a[mtl], Ab + ((mtl * 4 + ks) << 9));
#pragma unroll
                for (int mtl = 0; mtl < 4; ++mtl)
#pragma unroll
                    for (int ntl = 0; ntl < 4; ++ntl)
                        mma8(acc[mtl][ntl],
                             a[mtl][0], a[mtl][1], a[mtl][2], a[mtl][3],
                             bp[ntl][kin * 2], bp[ntl][kin * 2 + 1]);
            }
        }
        __syncthreads();
    }

    // ---- epilogue1: h1 = tf32(relu(C + b1)) stored in GEMM2 A-fragment order ----
    {
        const float* b1s = (const float*)(smem + B1S);
#pragma unroll
        for (int mtl = 0; mtl < 4; ++mtl) {
#pragma unroll
            for (int ntl = 0; ntl < 4; ++ntl) {
                const int r0 = warp_m * 64 + mtl * 16 + g;
                const int c0 = warp_n * 32 + ntl * 8 + 2 * t4;
                const float bb0 = b1s[c0], bb1 = b1s[c0 + 1];
                *(uint32_t*)(smem + H_OFF + h_addr(r0,     c0    )) = f2tf(fmaxf(acc[mtl][ntl][0] + bb0, 0.f));
                *(uint32_t*)(smem + H_OFF + h_addr(r0,     c0 + 1)) = f2tf(fmaxf(acc[mtl][ntl][1] + bb1, 0.f));
                *(uint32_t*)(smem + H_OFF + h_addr(r0 + 8, c0    )) = f2tf(fmaxf(acc[mtl][ntl][2] + bb0, 0.f));
                *(uint32_t*)(smem + H_OFF + h_addr(r0 + 8, c0 + 1)) = f2tf(fmaxf(acc[mtl][ntl][3] + bb1, 0.f));
            }
        }
    }
    __syncthreads();

    // =================== GEMM2: D = h1 @ W2 (K=128), warp tile 64x16 ===================
    float a2[4][2][4];
#pragma unroll
    for (int i = 0; i < 4; ++i)
#pragma unroll
        for (int j = 0; j < 2; ++j)
#pragma unroll
            for (int c = 0; c < 4; ++c) a2[i][j][c] = 0.f;

    {
        const uint32_t Hb  = sb + H_OFF  + ((warp_m * 64) << 9) + lane * 16;
        const uint32_t W2b = sb + W2_OFF + ((warp_n * 16) << 9) + lane * 16;
#pragma unroll
        for (int ksp = 0; ksp < 8; ++ksp) {
            uint32_t bp[2][4];
#pragma unroll
            for (int ntl = 0; ntl < 2; ++ntl)
                LDS128(bp[ntl], W2b + ((ntl * 8 + ksp) << 9));
#pragma unroll
            for (int kin = 0; kin < 2; ++kin) {
                const int ks = ksp * 2 + kin;
                uint32_t a[4][4];
#pragma unroll
                for (int mtl = 0; mtl < 4; ++mtl)
                    LDS128(a[mtl], Hb + ((mtl * 16 + ks) << 9));
#pragma unroll
                for (int mtl = 0; mtl < 4; ++mtl)
#pragma unroll
                    for (int ntl = 0; ntl < 2; ++ntl)
                        mma8(a2[mtl][ntl],
                             a[mtl][0], a[mtl][1], a[mtl][2], a[mtl][3],
                             bp[ntl][kin * 2], bp[ntl][kin * 2 + 1]);
            }
        }
    }

    // =================== epilogue2: scores = relu(D + b2) . W3 (+b3) ===================
    {
        const float* b2s = (const float*)(smem + B2S);
        const float* w3s = (const float*)(smem + W3S);
        float* oacc = (float*)(smem + OACC);
#pragma unroll
        for (int mtl = 0; mtl < 4; ++mtl) {
            float plo = 0.f, phi = 0.f;
#pragma unroll
            for (int ntl = 0; ntl < 2; ++ntl) {
                const int c0 = warp_n * 16 + ntl * 8 + 2 * t4;
                const float w0 = w3s[c0], w1v = w3s[c0 + 1];
                const float bb0 = b2s[c0], bb1 = b2s[c0 + 1];
                plo += fmaxf(a2[mtl][ntl][0] + bb0, 0.f) * w0
                     + fmaxf(a2[mtl][ntl][1] + bb1, 0.f) * w1v;
                phi += fmaxf(a2[mtl][ntl][2] + bb0, 0.f) * w0
                     + fmaxf(a2[mtl][ntl][3] + bb1, 0.f) * w1v;
            }
            plo += __shfl_xor_sync(0xffffffffu, plo, 1);
            plo += __shfl_xor_sync(0xffffffffu, plo, 2);
            phi += __shfl_xor_sync(0xffffffffu, phi, 1);
            phi += __shfl_xor_sync(0xffffffffu, phi, 2);
            if (t4 == 0) {
                const int r = warp_m * 64 + mtl * 16 + g;
                oacc[r * 4 + warp_n]       = plo;
                oacc[(r + 8) * 4 + warp_n] = phi;
            }
        }
    }
    __syncthreads();

    if (tid < TILE_M && tid < rem) {
        const float* oa = (const float*)(smem + OACC) + tid * 4;
        out[tile0 + tid] = oa[0] + oa[1] + oa[2] + oa[3] + b3[0];
    }
}

extern "C" void kernel_launch(void* const* d_in, const int* in_sizes, int n_in,
                              void* d_out, int out_size)
{
    const float* z  = (const float*)d_in[0];
    const void*  ei = d_in[1];
    const float* W1 = (const float*)d_in[2];
    const float* b1 = (const float*)d_in[3];
    const float* W2 = (const float*)d_in[4];
    const float* b2 = (const float*)d_in[5];
    const float* W3 = (const float*)d_in[6];
    const float* b3 = (const float*)d_in[7];
    float* out = (float*)d_out;

    cudaFuncSetAttribute(lp_mma_kernel, cudaFuncAttributeMaxDynamicSharedMemorySize,
                         SMEM_TOTAL);

    dim3 grid((E_TOTAL + TILE_M - 1) / TILE_M);   // 4883 CTAs
    lp_mma_kernel<<<grid, THREADS, SMEM_TOTAL>>>(z, ei, W1, b1, W2, b2, W3, b3, out);
}

// round 9
// speedup vs baseline: 1.5385x; 1.0589x over previous
#include <cuda_runtime.h>
#include <cstdint>

#define E_TOTAL 625000
#define DZ      128
#define HH      128
#define HQ      64
#define TILE_M  128
#define THREADS 256

// ---------------- SMEM layout (byte offsets) ----------------
// GEMM1 stage: A slices 2 x 8 KB, B slices 2 x 8 KB  (K-slice = 16)
// After GEMM1: same 32 KB region holds W2 fragments (union)
// H (relu(h1), GEMM2-A fragment order): 64 KB
#define A0_OFF  0
#define A1_OFF  8192
#define B0_OFF  16384
#define B1_OFF  24576
#define W2F_OFF 0
#define H_OFF   32768
#define MISC    98304
#define SRCI    (MISC + 0)
#define DSTI    (MISC + 512)
#define B1S     (MISC + 1024)
#define B2S     (MISC + 1536)
#define W3S     (MISC + 1792)
#define OACC    (MISC + 2048)   // 128 rows x 4 warp-cols x f32
#define SMEM_TOTAL (MISC + 4096)   // 102400 B -> 2 CTAs/SM

// ---------------- helpers ----------------
__device__ __forceinline__ uint32_t smem_u32(const void* p) {
    uint32_t a;
    asm("{ .reg .u64 t; cvta.to.shared.u64 t, %1; cvt.u32.u64 %0, t; }"
        : "=r"(a) : "l"(p));
    return a;
}

__device__ __forceinline__ uint32_t f2tf(float f) {
    uint32_t u;
    asm("cvt.rna.tf32.f32 %0, %1;" : "=r"(u) : "f"(f));
    return u;
}

// m16n8k8 tf32 mma, fp32 accumulate (base sm_80 PTX — OK on plain sm_103)
__device__ __forceinline__ void mma8(float* d,
                                     uint32_t a0, uint32_t a1, uint32_t a2, uint32_t a3,
                                     uint32_t b0, uint32_t b1) {
    asm volatile(
        "mma.sync.aligned.m16n8k8.row.col.f32.tf32.tf32.f32 "
        "{%0,%1,%2,%3}, {%4,%5,%6,%7}, {%8,%9}, {%0,%1,%2,%3};"
        : "+f"(d[0]), "+f"(d[1]), "+f"(d[2]), "+f"(d[3])
        : "r"(a0), "r"(a1), "r"(a2), "r"(a3), "r"(b0), "r"(b1));
}

#define LDS128(r, addr)                                                        \
    asm volatile("ld.shared.v4.b32 {%0,%1,%2,%3}, [%4];"                       \
        : "=r"((r)[0]), "=r"((r)[1]), "=r"((r)[2]), "=r"((r)[3]) : "r"(addr))

// ---- fragment-order address maps (byte offsets within region) ----
// A slice (128 rows x 16 k): unit = ((m>>4)*2 + (k>>3))*32 + (m&7)*4 + (k&3)
__device__ __forceinline__ int a_addr16(int m, int k) {
    return ((((m >> 4) * 2 + (k >> 3)) * 32 + (m & 7) * 4 + (k & 3)) << 4)
         + ((k & 4) ? 8 : 0) + ((m & 8) ? 4 : 0);
}
// B slice (16 k x 128 n): unit = (n>>3)*32 + (n&7)*4 + (k&3); 16B = k sub {0,4,8,12}
__device__ __forceinline__ int b_addr16(int k, int n) {
    return (((n >> 3) * 32 + (n & 7) * 4 + (k & 3)) << 4) + (k & 12);
}
// H (128 x 128), GEMM2-A fragment order
__device__ __forceinline__ int h_addr(int m, int k) {
    return ((((m >> 4) * 16 + (k >> 3)) * 32 + (m & 7) * 4 + (k & 3)) << 4)
         + ((k & 4) ? 8 : 0) + ((m & 8) ? 4 : 0);
}
// W2 fragments (128 k x 64 n)
__device__ __forceinline__ int w2_addr(int k, int n) {
    return ((((n >> 3) * 8 + (k >> 4)) * 32 + (n & 7) * 4 + (k & 3)) << 4)
         + (((k >> 3) & 1) << 3) + ((k & 4) ? 4 : 0);
}

// ---------------- kernel ----------------
__global__ void __launch_bounds__(THREADS, 2)
lp_mma_kernel(const float* __restrict__ z,
              const void*  __restrict__ ei_raw,
              const float* __restrict__ W1,
              const float* __restrict__ b1,
              const float* __restrict__ W2,
              const float* __restrict__ b2,
              const float* __restrict__ W3,
              const float* __restrict__ b3,
              float* __restrict__ out)
{
    extern __shared__ char smem[];
    const uint32_t sb  = smem_u32(smem);
    const int tid      = threadIdx.x;
    const int lane     = tid & 31;
    const int wid      = tid >> 5;
    const int g        = lane >> 2;
    const int t4       = lane & 3;
    const int warp_m   = wid & 1;        // 2 m-warps (64 rows)
    const int warp_n   = wid >> 1;       // 4 n-warps (32 cols)
    const int tile0    = blockIdx.x * TILE_M;
    const int rem      = min(TILE_M, E_TOTAL - tile0);

    // ---- edge_index dtype sniff (int64 vs int32) + index staging ----
    const int* e32 = reinterpret_cast<const int*>(ei_raw);
    int hiw = 0;
#pragma unroll
    for (int i = 0; i < 32; ++i) hiw |= e32[2 * i + 1];
    const bool is64 = (hiw == 0);

    if (tid < TILE_M) {
        int e = tile0 + ((tid < rem) ? tid : 0);
        int si, di;
        if (is64) {
            const long long* e64 = reinterpret_cast<const long long*>(ei_raw);
            si = (int)e64[e];
            di = (int)e64[E_TOTAL + e];
        } else {
            si = e32[e];
            di = e32[E_TOTAL + e];
        }
        ((int*)(smem + SRCI))[tid] = si;
        ((int*)(smem + DSTI))[tid] = di;
        ((float*)(smem + B1S))[tid] = b1[tid];
    }
    if (tid < HQ) {
        ((float*)(smem + B2S))[tid] = b2[tid];
        ((float*)(smem + W3S))[tid] = W3[tid];
    }
    __syncthreads();

    // ---- loaders (K-slice = 16) ----
    // A: lane -> k (bank-friendly stores: 2-way instead of 8-way)
    auto load_A = [&](int step, int off) {
        const int kk   = tid & 15;           // k within slice
        const int moct = tid >> 4;           // row octet 0..15
        const int kg   = step * 16 + kk;     // global k (slice never straddles halves)
        const int* idx = (const int*)(smem + (kg < DZ ? SRCI : DSTI));
        const float* zc = z + (kg & (DZ - 1));
        char* base = smem + off;
#pragma unroll
        for (int i = 0; i < 8; ++i) {
            const int m = moct * 8 + i;
            float v = __ldg(zc + (size_t)idx[m] * DZ);
            *(uint32_t*)(base + a_addr16(m, kk)) = f2tf(v);
        }
    };
    // B: W1 slice (16 k x 128 n)
    auto load_B = [&](int step, int off) {
        const int kk = tid & 15;
        const int nh = tid >> 4;             // n octet 0..15
        const float* gp = W1 + (size_t)(step * 16 + kk) * HH + nh * 8;
        char* base = smem + off;
#pragma unroll
        for (int q = 0; q < 2; ++q) {
            float4 v = __ldg(reinterpret_cast<const float4*>(gp + q * 4));
            const int n0 = nh * 8 + q * 4;
            *(uint32_t*)(base + b_addr16(kk, n0 + 0)) = f2tf(v.x);
            *(uint32_t*)(base + b_addr16(kk, n0 + 1)) = f2tf(v.y);
            *(uint32_t*)(base + b_addr16(kk, n0 + 2)) = f2tf(v.z);
            *(uint32_t*)(base + b_addr16(kk, n0 + 3)) = f2tf(v.w);
        }
    };

    load_A(0, A0_OFF);
    load_B(0, B0_OFF);
    __syncthreads();

    // =================== GEMM1: C = [z_i|z_j] @ W1 (K=256, 16 slices) ===================
    float acc[4][4][4];
#pragma unroll
    for (int i = 0; i < 4; ++i)
#pragma unroll
        for (int j = 0; j < 4; ++j)
#pragma unroll
            for (int c = 0; c < 4; ++c) acc[i][j][c] = 0.f;

#pragma unroll 1
    for (int step = 0; step < 16; ++step) {
        const int cur = step & 1;
        if (step < 15) {                      // prefetch next slice into other buffer
            load_A(step + 1, cur ? A0_OFF : A1_OFF);
            load_B(step + 1, cur ? B0_OFF : B1_OFF);
        }
        const uint32_t Ab = sb + (cur ? A1_OFF : A0_OFF) + warp_m * 4096 + lane * 16;
        const uint32_t Bb = sb + (cur ? B1_OFF : B0_OFF) + warp_n * 2048 + lane * 16;

        uint32_t bp[4][4];
#pragma unroll
        for (int ntl = 0; ntl < 4; ++ntl)
            LDS128(bp[ntl], Bb + (ntl << 9));
#pragma unroll
        for (int kb = 0; kb < 2; ++kb) {
            uint32_t a[4][4];
#pragma unroll
            for (int mtl = 0; mtl < 4; ++mtl)
                LDS128(a[mtl], Ab + ((mtl * 2 + kb) << 9));
#pragma unroll
            for (int mtl = 0; mtl < 4; ++mtl)
#pragma unroll
                for (int ntl = 0; ntl < 4; ++ntl)
                    mma8(acc[mtl][ntl],
                         a[mtl][0], a[mtl][1], a[mtl][2], a[mtl][3],
                         bp[ntl][kb * 2], bp[ntl][kb * 2 + 1]);
        }
        __syncthreads();
    }

    // ---- epilogue1: h1 = tf32(relu(C + b1)) in GEMM2 A-fragment order ----
    {
        const float* b1s = (const float*)(smem + B1S);
#pragma unroll
        for (int mtl = 0; mtl < 4; ++mtl) {
#pragma unroll
            for (int ntl = 0; ntl < 4; ++ntl) {
                const int r0 = warp_m * 64 + mtl * 16 + g;
                const int c0 = warp_n * 32 + ntl * 8 + 2 * t4;
                const float bb0 = b1s[c0], bb1 = b1s[c0 + 1];
                *(uint32_t*)(smem + H_OFF + h_addr(r0,     c0    )) = f2tf(fmaxf(acc[mtl][ntl][0] + bb0, 0.f));
                *(uint32_t*)(smem + H_OFF + h_addr(r0,     c0 + 1)) = f2tf(fmaxf(acc[mtl][ntl][1] + bb1, 0.f));
                *(uint32_t*)(smem + H_OFF + h_addr(r0 + 8, c0    )) = f2tf(fmaxf(acc[mtl][ntl][2] + bb0, 0.f));
                *(uint32_t*)(smem + H_OFF + h_addr(r0 + 8, c0 + 1)) = f2tf(fmaxf(acc[mtl][ntl][3] + bb1, 0.f));
            }
        }
    }

    // ---- W2 fragments into the dead A/B region (union) ----
    {
        const int k  = tid >> 1;
        const int nh = tid & 1;
        const float* gp = W2 + (size_t)k * HQ + nh * 32;
        char* base = smem + W2F_OFF;
#pragma unroll
        for (int q = 0; q < 8; ++q) {
            float4 v = __ldg(reinterpret_cast<const float4*>(gp + q * 4));
            const int n0 = nh * 32 + q * 4;
            *(uint32_t*)(base + w2_addr(k, n0 + 0)) = f2tf(v.x);
            *(uint32_t*)(base + w2_addr(k, n0 + 1)) = f2tf(v.y);
            *(uint32_t*)(base + w2_addr(k, n0 + 2)) = f2tf(v.z);
            *(uint32_t*)(base + w2_addr(k, n0 + 3)) = f2tf(v.w);
        }
    }
    __syncthreads();

    // =================== GEMM2: D = h1 @ W2 (K=128), warp tile 64x16 ===================
    float a2[4][2][4];
#pragma unroll
    for (int i = 0; i < 4; ++i)
#pragma unroll
        for (int j = 0; j < 2; ++j)
#pragma unroll
            for (int c = 0; c < 4; ++c) a2[i][j][c] = 0.f;

    {
        const uint32_t Hb  = sb + H_OFF  + warp_m * 32768 + lane * 16;
        const uint32_t W2b = sb + W2F_OFF + ((warp_n * 16) << 9) + lane * 16;
#pragma unroll
        for (int ksp = 0; ksp < 8; ++ksp) {
            uint32_t bp[2][4];
#pragma unroll
            for (int ntl = 0; ntl < 2; ++ntl)
                LDS128(bp[ntl], W2b + ((ntl * 8 + ksp) << 9));
#pragma unroll
            for (int kin = 0; kin < 2; ++kin) {
                const int ks = ksp * 2 + kin;
                uint32_t a[4][4];
#pragma unroll
                for (int mtl = 0; mtl < 4; ++mtl)
                    LDS128(a[mtl], Hb + ((mtl * 16 + ks) << 9));
#pragma unroll
                for (int mtl = 0; mtl < 4; ++mtl)
#pragma unroll
                    for (int ntl = 0; ntl < 2; ++ntl)
                        mma8(a2[mtl][ntl],
                             a[mtl][0], a[mtl][1], a[mtl][2], a[mtl][3],
                             bp[ntl][kin * 2], bp[ntl][kin * 2 + 1]);
            }
        }
    }

    // =================== epilogue2: scores = relu(D + b2) . W3 (+b3) ===================
    {
        const float* b2s = (const float*)(smem + B2S);
        const float* w3s = (const float*)(smem + W3S);
        float* oacc = (float*)(smem + OACC);
#pragma unroll
        for (int mtl = 0; mtl < 4; ++mtl) {
            float plo = 0.f, phi = 0.f;
#pragma unroll
            for (int ntl = 0; ntl < 2; ++ntl) {
                const int c0 = warp_n * 16 + ntl * 8 + 2 * t4;
                const float w0 = w3s[c0], w1v = w3s[c0 + 1];
                const float bb0 = b2s[c0], bb1 = b2s[c0 + 1];
                plo += fmaxf(a2[mtl][ntl][0] + bb0, 0.f) * w0
                     + fmaxf(a2[mtl][ntl][1] + bb1, 0.f) * w1v;
                phi += fmaxf(a2[mtl][ntl][2] + bb0, 0.f) * w0
                     + fmaxf(a2[mtl][ntl][3] + bb1, 0.f) * w1v;
            }
            plo += __shfl_xor_sync(0xffffffffu, plo, 1);
            plo += __shfl_xor_sync(0xffffffffu, plo, 2);
            phi += __shfl_xor_sync(0xffffffffu, phi, 1);
            phi += __shfl_xor_sync(0xffffffffu, phi, 2);
            if (t4 == 0) {
                const int r = warp_m * 64 + mtl * 16 + g;
                oacc[r * 4 + warp_n]       = plo;
                oacc[(r + 8) * 4 + warp_n] = phi;
            }
        }
    }
    __syncthreads();

    if (tid < TILE_M && tid < rem) {
        const float* oa = (const float*)(smem + OACC) + tid * 4;
        out[tile0 + tid] = oa[0] + oa[1] + oa[2] + oa[3] + b3[0];
    }
}

extern "C" void kernel_launch(void* const* d_in, const int* in_sizes, int n_in,
                              void* d_out, int out_size)
{
    const float* z  = (const float*)d_in[0];
    const void*  ei = d_in[1];
    const float* W1 = (const float*)d_in[2];
    const float* b1 = (const float*)d_in[3];
    const float* W2 = (const float*)d_in[4];
    const float* b2 = (const float*)d_in[5];
    const float* W3 = (const float*)d_in[6];
    const float* b3 = (const float*)d_in[7];
    float* out = (float*)d_out;

    cudaFuncSetAttribute(lp_mma_kernel, cudaFuncAttributeMaxDynamicSharedMemorySize,
                         SMEM_TOTAL);

    dim3 grid((E_TOTAL + TILE_M - 1) / TILE_M);   // 4883 CTAs
    lp_mma_kernel<<<grid, THREADS, SMEM_TOTAL>>>(z, ei, W1, b1, W2, b2, W3, b3, out);
}

// round 10
// speedup vs baseline: 3.3917x; 2.2046x over previous
#include <cuda_runtime.h>
#include <cstdint>

#define E_TOTAL 625000
#define N_NODES 50000
#define DZ      128
#define HH      128
#define HQ      64
#define TILE_M  128
#define THREADS 256

// ---------------- global scratch (preprocessed once per launch) ----------------
__device__ float    g_ztf[(size_t)N_NODES * DZ];   // z rounded to tf32 bits
__device__ uint32_t g_w1f[256 * 128];              // W1 in MMA fragment layout (8 slices of 32k)
__device__ uint32_t g_w2f[128 * 64];               // W2 in MMA fragment layout

// ---------------- SMEM layout ----------------
#define A0_OFF  0
#define A1_OFF  16384
#define B0_OFF  32768
#define B1_OFF  49152
#define H_OFF   0            // overlays A/B after GEMM1
#define W2F_OFF 65536
#define MISC    98304
#define SRCI    (MISC + 0)
#define DSTI    (MISC + 512)
#define B1S     (MISC + 1024)
#define B2S     (MISC + 1536)
#define W3S     (MISC + 1792)
#define OACC    (MISC + 2048)
#define SMEM_TOTAL (MISC + 4096)   // 102400 B -> 2 CTAs/SM

// ---------------- helpers ----------------
__device__ __forceinline__ uint32_t smem_u32(const void* p) {
    uint32_t a;
    asm("{ .reg .u64 t; cvta.to.shared.u64 t, %1; cvt.u32.u64 %0, t; }"
        : "=r"(a) : "l"(p));
    return a;
}
__device__ __forceinline__ uint32_t f2tf(float f) {
    uint32_t u;
    asm("cvt.rna.tf32.f32 %0, %1;" : "=r"(u) : "f"(f));
    return u;
}
__device__ __forceinline__ void mma8(float* d,
                                     uint32_t a0, uint32_t a1, uint32_t a2, uint32_t a3,
                                     uint32_t b0, uint32_t b1) {
    asm volatile(
        "mma.sync.aligned.m16n8k8.row.col.f32.tf32.tf32.f32 "
        "{%0,%1,%2,%3}, {%4,%5,%6,%7}, {%8,%9}, {%0,%1,%2,%3};"
        : "+f"(d[0]), "+f"(d[1]), "+f"(d[2]), "+f"(d[3])
        : "r"(a0), "r"(a1), "r"(a2), "r"(a3), "r"(b0), "r"(b1));
}
#define LDS128(r, addr)                                                        \
    asm volatile("ld.shared.v4.b32 {%0,%1,%2,%3}, [%4];"                       \
        : "=r"((r)[0]), "=r"((r)[1]), "=r"((r)[2]), "=r"((r)[3]) : "r"(addr))
#define CP16(dst, src)                                                         \
    asm volatile("cp.async.cg.shared.global [%0], [%1], 16;"                   \
        :: "r"(dst), "l"(src) : "memory")
#define CP_COMMIT() asm volatile("cp.async.commit_group;" ::: "memory")
#define CP_WAIT0()  asm volatile("cp.async.wait_group 0;" ::: "memory")

// ---- fragment-layout address maps (byte offsets) ----
// A slice 128m x 32k
__host__ __device__ __forceinline__ int a_addr32(int m, int k) {
    return ((((m >> 4) * 4 + (k >> 3)) * 32 + (m & 7) * 4 + (k & 3)) << 4)
         + ((k & 4) ? 8 : 0) + ((m & 8) ? 4 : 0);
}
// B slice 32k x 128n
__host__ __device__ __forceinline__ int b_addr32(int k, int n) {
    return ((((n >> 3) * 2 + (k >> 4)) * 32 + (n & 7) * 4 + (k & 3)) << 4) + (k & 12);
}
// H 128m x 128k
__device__ __forceinline__ int h_addr(int m, int k) {
    return ((((m >> 4) * 16 + (k >> 3)) * 32 + (m & 7) * 4 + (k & 3)) << 4)
         + ((k & 4) ? 8 : 0) + ((m & 8) ? 4 : 0);
}
// W2 128k x 64n
__host__ __device__ __forceinline__ int w2_addr(int k, int n) {
    return ((((n >> 3) * 8 + (k >> 4)) * 32 + (n & 7) * 4 + (k & 3)) << 4)
         + (((k >> 3) & 1) << 3) + ((k & 4) ? 4 : 0);
}

// ---------------- prep kernel: convert z, build weight fragments ----------------
__global__ void __launch_bounds__(256)
prep_kernel(const float* __restrict__ z,
            const float* __restrict__ W1,
            const float* __restrict__ W2)
{
    const int b = blockIdx.x;
    if (b == 0) {
        for (int i = threadIdx.x; i < 256 * 128; i += 256) {
            const int k = i >> 7, n = i & 127;
            g_w1f[((k >> 5) * 16384 + b_addr32(k & 31, n)) >> 2] =
                f2tf(__ldg(W1 + (size_t)k * HH + n));
        }
        for (int i = threadIdx.x; i < 128 * 64; i += 256) {
            const int k = i >> 6, n = i & 63;
            g_w2f[w2_addr(k, n) >> 2] = f2tf(__ldg(W2 + (size_t)k * HQ + n));
        }
    } else {
        const size_t base = (size_t)(b - 1) * 1024 + threadIdx.x * 4;
        float4 v = __ldg(reinterpret_cast<const float4*>(z + base));
        float4 o;
        o.x = __uint_as_float(f2tf(v.x));
        o.y = __uint_as_float(f2tf(v.y));
        o.z = __uint_as_float(f2tf(v.z));
        o.w = __uint_as_float(f2tf(v.w));
        *reinterpret_cast<float4*>(g_ztf + base) = o;
    }
}

// ---------------- main kernel ----------------
__global__ void __launch_bounds__(THREADS, 2)
lp_mma_kernel(const void*  __restrict__ ei_raw,
              const float* __restrict__ b1,
              const float* __restrict__ b2,
              const float* __restrict__ W3,
              const float* __restrict__ b3,
              float* __restrict__ out)
{
    extern __shared__ char smem[];
    const uint32_t sb  = smem_u32(smem);
    const int tid      = threadIdx.x;
    const int lane     = tid & 31;
    const int wid      = tid >> 5;
    const int g        = lane >> 2;
    const int t4       = lane & 3;
    const int warp_m   = wid & 1;        // 2 m-warps (64 rows)
    const int warp_n   = wid >> 1;       // 4 n-warps (32 cols)
    const int tile0    = blockIdx.x * TILE_M;
    const int rem      = min(TILE_M, E_TOTAL - tile0);

    // ---- edge_index dtype sniff + staging ----
    const int* e32 = reinterpret_cast<const int*>(ei_raw);
    int hiw = 0;
#pragma unroll
    for (int i = 0; i < 32; ++i) hiw |= e32[2 * i + 1];
    const bool is64 = (hiw == 0);

    if (tid < TILE_M) {
        int e = tile0 + ((tid < rem) ? tid : 0);
        int si, di;
        if (is64) {
            const long long* e64 = reinterpret_cast<const long long*>(ei_raw);
            si = (int)e64[e];
            di = (int)e64[E_TOTAL + e];
        } else {
            si = e32[e];
            di = e32[E_TOTAL + e];
        }
        ((int*)(smem + SRCI))[tid] = si;
        ((int*)(smem + DSTI))[tid] = di;
        ((float*)(smem + B1S))[tid] = b1[tid];
    }
    if (tid < HQ) {
        ((float*)(smem + B2S))[tid] = b2[tid];
        ((float*)(smem + W3S))[tid] = W3[tid];
    }
    __syncthreads();

    // ---- W2 fragments upfront (off critical path) ----
    {
        const uint32_t dst = sb + W2F_OFF + tid * 16;
        const char* src = (const char*)g_w2f + tid * 16;
#pragma unroll
        for (int i = 0; i < 8; ++i) CP16(dst + i * 4096, src + i * 4096);
    }
    // ---- B slice copier (pure cp.async, contiguous) ----
    auto cp_B = [&](int step, int off) {
        const uint32_t dst = sb + off + tid * 16;
        const char* src = (const char*)g_w1f + step * 16384 + tid * 16;
#pragma unroll
        for (int i = 0; i < 4; ++i) CP16(dst + i * 4096, src + i * 4096);
    };

    // ---- A gather: coalesced LDG into regs / deferred STS ----
    const int kk   = lane & 15;
    const int roff = lane >> 4;
    auto ldA = [&](int step, uint32_t areg[16]) {
        const int* idx = (const int*)(smem + ((step >= 4) ? DSTI : SRCI));
        const int kbase = (step * 32) & (DZ - 1);
#pragma unroll
        for (int i = 0; i < 8; ++i) {
            const int m = wid * 16 + i * 2 + roff;
            const float* zr = g_ztf + (size_t)idx[m] * DZ + kbase + kk;
            areg[i * 2 + 0] = __float_as_uint(__ldg(zr));
            areg[i * 2 + 1] = __float_as_uint(__ldg(zr + 16));
        }
    };
    auto stA = [&](const uint32_t areg[16], int off) {
        char* base = smem + off;
#pragma unroll
        for (int i = 0; i < 8; ++i) {
            const int m = wid * 16 + i * 2 + roff;
            *(uint32_t*)(base + a_addr32(m, kk))      = areg[i * 2 + 0];
            *(uint32_t*)(base + a_addr32(m, kk + 16)) = areg[i * 2 + 1];
        }
    };

    uint32_t areg[16];
    cp_B(0, B0_OFF);
    CP_COMMIT();
    ldA(0, areg);
    stA(areg, A0_OFF);
    CP_WAIT0();
    __syncthreads();

    // =================== GEMM1: C = [z_i|z_j] @ W1 (K=256, 8 slices of 32) ==========
    float acc[4][4][4];
#pragma unroll
    for (int i = 0; i < 4; ++i)
#pragma unroll
        for (int j = 0; j < 4; ++j)
#pragma unroll
            for (int c = 0; c < 4; ++c) acc[i][j][c] = 0.f;

#pragma unroll 1
    for (int step = 0; step < 8; ++step) {
        const int cur = step & 1;
        const uint32_t Ab = sb + (cur ? A1_OFF : A0_OFF) + warp_m * 8192 + lane * 16;
        const uint32_t Bb = sb + (cur ? B1_OFF : B0_OFF) + warp_n * 4096 + lane * 16;

        if (step < 7) {
            cp_B(step + 1, cur ? B0_OFF : B1_OFF);
            CP_COMMIT();
            ldA(step + 1, areg);            // LDG latency overlaps compute below
        }

#pragma unroll
        for (int kb = 0; kb < 2; ++kb) {
            uint32_t bp[4][4];
#pragma unroll
            for (int ntl = 0; ntl < 4; ++ntl)
                LDS128(bp[ntl], Bb + ((ntl * 2 + kb) << 9));
#pragma unroll
            for (int kin = 0; kin < 2; ++kin) {
                const int ks = kb * 2 + kin;
                uint32_t a[4][4];
#pragma unroll
                for (int mtl = 0; mtl < 4; ++mtl)
                    LDS128(a[mtl], Ab + ((mtl * 4 + ks) << 9));
#pragma unroll
                for (int mtl = 0; mtl < 4; ++mtl)
#pragma unroll
                    for (int ntl = 0; ntl < 4; ++ntl)
                        mma8(acc[mtl][ntl],
                             a[mtl][0], a[mtl][1], a[mtl][2], a[mtl][3],
                             bp[ntl][kin * 2], bp[ntl][kin * 2 + 1]);
            }
        }

        if (step < 7) {
            stA(areg, cur ? A0_OFF : A1_OFF);
            CP_WAIT0();
        }
        __syncthreads();
    }

    // ---- epilogue1: h1 = tf32(relu(C + b1)) into H (overlays A/B region) ----
    {
        const float* b1s = (const float*)(smem + B1S);
#pragma unroll
        for (int mtl = 0; mtl < 4; ++mtl) {
#pragma unroll
            for (int ntl = 0; ntl < 4; ++ntl) {
                const int r0 = warp_m * 64 + mtl * 16 + g;
                const int c0 = warp_n * 32 + ntl * 8 + 2 * t4;
                const float bb0 = b1s[c0], bb1 = b1s[c0 + 1];
                *(uint32_t*)(smem + H_OFF + h_addr(r0,     c0    )) = f2tf(fmaxf(acc[mtl][ntl][0] + bb0, 0.f));
                *(uint32_t*)(smem + H_OFF + h_addr(r0,     c0 + 1)) = f2tf(fmaxf(acc[mtl][ntl][1] + bb1, 0.f));
                *(uint32_t*)(smem + H_OFF + h_addr(r0 + 8, c0    )) = f2tf(fmaxf(acc[mtl][ntl][2] + bb0, 0.f));
                *(uint32_t*)(smem + H_OFF + h_addr(r0 + 8, c0 + 1)) = f2tf(fmaxf(acc[mtl][ntl][3] + bb1, 0.f));
            }
        }
    }
    __syncthreads();

    // =================== GEMM2: D = h1 @ W2 (K=128), warp tile 64x16 ===================
    float a2[4][2][4];
#pragma unroll
    for (int i = 0; i < 4; ++i)
#pragma unroll
        for (int j = 0; j < 2; ++j)
#pragma unroll
            for (int c = 0; c < 4; ++c) a2[i][j][c] = 0.f;

    {
        const uint32_t Hb  = sb + H_OFF   + warp_m * 32768 + lane * 16;
        const uint32_t W2b = sb + W2F_OFF + ((warp_n * 16) << 9) + lane * 16;
#pragma unroll
        for (int ksp = 0; ksp < 8; ++ksp) {
            uint32_t bp[2][4];
#pragma unroll
            for (int ntl = 0; ntl < 2; ++ntl)
                LDS128(bp[ntl], W2b + ((ntl * 8 + ksp) << 9));
#pragma unroll
            for (int kin = 0; kin < 2; ++kin) {
                const int ks = ksp * 2 + kin;
                uint32_t a[4][4];
#pragma unroll
                for (int mtl = 0; mtl < 4; ++mtl)
                    LDS128(a[mtl], Hb + ((mtl * 16 + ks) << 9));
#pragma unroll
                for (int mtl = 0; mtl < 4; ++mtl)
#pragma unroll
                    for (int ntl = 0; ntl < 2; ++ntl)
                        mma8(a2[mtl][ntl],
                             a[mtl][0], a[mtl][1], a[mtl][2], a[mtl][3],
                             bp[ntl][kin * 2], bp[ntl][kin * 2 + 1]);
            }
        }
    }

    // =================== epilogue2: scores = relu(D + b2) . W3 (+b3) ===================
    {
        const float* b2s = (const float*)(smem + B2S);
        const float* w3s = (const float*)(smem + W3S);
        float* oacc = (float*)(smem + OACC);
#pragma unroll
        for (int mtl = 0; mtl < 4; ++mtl) {
            float plo = 0.f, phi = 0.f;
#pragma unroll
            for (int ntl = 0; ntl < 2; ++ntl) {
                const int c0 = warp_n * 16 + ntl * 8 + 2 * t4;
                const float w0 = w3s[c0], w1v = w3s[c0 + 1];
                const float bb0 = b2s[c0], bb1 = b2s[c0 + 1];
                plo += fmaxf(a2[mtl][ntl][0] + bb0, 0.f) * w0
                     + fmaxf(a2[mtl][ntl][1] + bb1, 0.f) * w1v;
                phi += fmaxf(a2[mtl][ntl][2] + bb0, 0.f) * w0
                     + fmaxf(a2[mtl][ntl][3] + bb1, 0.f) * w1v;
            }
            plo += __shfl_xor_sync(0xffffffffu, plo, 1);
            plo += __shfl_xor_sync(0xffffffffu, plo, 2);
            phi += __shfl_xor_sync(0xffffffffu, phi, 1);
            phi += __shfl_xor_sync(0xffffffffu, phi, 2);
            if (t4 == 0) {
                const int r = warp_m * 64 + mtl * 16 + g;
                oacc[r * 4 + warp_n]       = plo;
                oacc[(r + 8) * 4 + warp_n] = phi;
            }
        }
    }
    __syncthreads();

    if (tid < TILE_M && tid < rem) {
        const float* oa = (const float*)(smem + OACC) + tid * 4;
        out[tile0 + tid] = oa[0] + oa[1] + oa[2] + oa[3] + b3[0];
    }
}

extern "C" void kernel_launch(void* const* d_in, const int* in_sizes, int n_in,
                              void* d_out, int out_size)
{
    const float* z  = (const float*)d_in[0];
    const void*  ei = d_in[1];
    const float* W1 = (const float*)d_in[2];
    const float* b1 = (const float*)d_in[3];
    const float* W2 = (const float*)d_in[4];
    const float* b2 = (const float*)d_in[5];
    const float* W3 = (const float*)d_in[6];
    const float* b3 = (const float*)d_in[7];
    float* out = (float*)d_out;

    // prep: blocks 1..6250 convert z (1024 floats each); block 0 builds W frags
    prep_kernel<<<6251, 256>>>(z, W1, W2);

    cudaFuncSetAttribute(lp_mma_kernel, cudaFuncAttributeMaxDynamicSharedMemorySize,
                         SMEM_TOTAL);
    dim3 grid((E_TOTAL + TILE_M - 1) / TILE_M);   // 4883 CTAs
    lp_mma_kernel<<<grid, THREADS, SMEM_TOTAL>>>(ei, b1, b2, W3, b3, out);
}